// round 1
// baseline (speedup 1.0000x reference)
#include <cuda_runtime.h>
#include <math_constants.h>

#define WML    64
#define BATCH  64
#define SENTS  40
#define DIM    512
#define NWORDS (SENTS * WML)   /* 2560 */
#define WSPLIT 8
#define WPC    (WML / WSPLIT)  /* 8 w-values per CTA, one per warp */

/* ------------------- scratch (static device memory; no allocs) -------- */
__device__ float g_qword[BATCH * DIM];
__device__ float g_qsent[BATCH * DIM];
__device__ float g_ssa[BATCH * SENTS];
__device__ float g_scores[BATCH * NWORDS];
__device__ float g_partM[BATCH * WSPLIT];
__device__ float g_partL[BATCH * WSPLIT];
__device__ float g_partAcc[BATCH * WSPLIT * DIM];
__device__ float g_c[BATCH * DIM];

/* ------------------- K0: q_word / q_sent projections ------------------ */
/* out[b][d] = sum_k src[b][k] * W[d][k];  grid (DIM/64, 2), 256 thr     */
__global__ void qproj_kernel(const float* __restrict__ src,
                             const float* __restrict__ Wword,
                             const float* __restrict__ Wsent) {
    const float* W   = blockIdx.y ? Wsent : Wword;
    float*       out = blockIdx.y ? g_qsent : g_qword;
    const int dt = blockIdx.x * 64;

    __shared__ float As[64][65];
    __shared__ float Bs[64][65];
    const int tid = threadIdx.x;
    const int tx = tid & 15, ty = tid >> 4;
    float acc[4][4] = {};

    for (int k0 = 0; k0 < DIM; k0 += 64) {
        for (int i = tid; i < 4096; i += 256) {
            int r = i >> 6, c = i & 63;
            As[r][c] = src[r * DIM + k0 + c];
            Bs[r][c] = W[(dt + r) * DIM + k0 + c];
        }
        __syncthreads();
        #pragma unroll 8
        for (int kk = 0; kk < 64; kk++) {
            float a[4], w[4];
            #pragma unroll
            for (int i = 0; i < 4; i++) a[i] = As[ty * 4 + i][kk];
            #pragma unroll
            for (int j = 0; j < 4; j++) w[j] = Bs[tx * 4 + j][kk];
            #pragma unroll
            for (int i = 0; i < 4; i++)
                #pragma unroll
                for (int j = 0; j < 4; j++) acc[i][j] += a[i] * w[j];
        }
        __syncthreads();
    }
    #pragma unroll
    for (int i = 0; i < 4; i++)
        #pragma unroll
        for (int j = 0; j < 4; j++)
            out[(ty * 4 + i) * DIM + dt + tx * 4 + j] = acc[i][j];
}

/* ------------------- K1: ssa[b][s] = (q_sent . sent_v) * static ------- */
__global__ void sentscore_kernel(const float* __restrict__ sent_bank,
                                 const float* __restrict__ static_attn) {
    const int b = blockIdx.x;
    const int tid = threadIdx.x;
    __shared__ float sq[DIM];
    for (int i = tid; i < DIM; i += 256) sq[i] = g_qsent[b * DIM + i];
    __syncthreads();

    const int wp = tid >> 5, ln = tid & 31;
    const float4* q4 = (const float4*)sq;
    for (int s = wp; s < SENTS; s += 8) {
        const float4* v4 = (const float4*)(sent_bank + ((size_t)s * BATCH + b) * DIM);
        float dot = 0.f;
        #pragma unroll
        for (int k = 0; k < 4; k++) {
            float4 q = q4[ln + 32 * k];
            float4 v = v4[ln + 32 * k];
            dot += q.x * v.x + q.y * v.y + q.z * v.z + q.w * v.w;
        }
        #pragma unroll
        for (int off = 16; off > 0; off >>= 1)
            dot += __shfl_xor_sync(0xffffffffu, dot, off);
        if (ln == 0) g_ssa[b * SENTS + s] = dot * static_attn[b * SENTS + s];
    }
}

/* ------------------- K2: fused score + online softmax + weighted sum -- */
/* grid (WSPLIT, BATCH), 256 thr. Warp wp owns w = sp*WPC + wp and       */
/* streams its contiguous (w,b) chunk: SENTS*DIM floats = 80KB.          */
__global__ void __launch_bounds__(256)
main_kernel(const float* __restrict__ word_bank,
            const int*   __restrict__ word_lengths) {
    const int b = blockIdx.y, sp = blockIdx.x;
    const int tid = threadIdx.x, wp = tid >> 5, ln = tid & 31;

    __shared__ float sq[DIM];
    __shared__ float sssa[SENTS];
    __shared__ int   swl[SENTS];
    __shared__ float racc[8][DIM];
    __shared__ float rm[8], rl[8];

    for (int i = tid; i < DIM; i += 256) sq[i] = g_qword[b * DIM + i];
    if (tid < SENTS) {
        sssa[tid] = g_ssa[b * SENTS + tid];
        swl[tid]  = word_lengths[b * SENTS + tid];
    }
    __syncthreads();

    const int w = sp * WPC + wp;
    const float4* q4 = (const float4*)sq;
    const float4 q0 = q4[ln], q1 = q4[ln + 32], q2 = q4[ln + 64], q3 = q4[ln + 96];
    const float* base = word_bank + ((size_t)w * BATCH + b) * (size_t)(SENTS * DIM);

    float m = -CUDART_INF_F, l = 0.f;
    float4 a0 = {0,0,0,0}, a1 = {0,0,0,0}, a2 = {0,0,0,0}, a3 = {0,0,0,0};

    for (int s = 0; s < SENTS; s++) {
        const float4* v4 = (const float4*)(base + (size_t)s * DIM);
        float4 v0 = v4[ln], v1 = v4[ln + 32], v2 = v4[ln + 64], v3 = v4[ln + 96];
        float dot = v0.x*q0.x + v0.y*q0.y + v0.z*q0.z + v0.w*q0.w
                  + v1.x*q1.x + v1.y*q1.y + v1.z*q1.z + v1.w*q1.w
                  + v2.x*q2.x + v2.y*q2.y + v2.z*q2.z + v2.w*q2.w
                  + v3.x*q3.x + v3.y*q3.y + v3.z*q3.z + v3.w*q3.w;
        #pragma unroll
        for (int off = 16; off > 0; off >>= 1)
            dot += __shfl_xor_sync(0xffffffffu, dot, off);

        const bool valid = (w < swl[s]);
        const float score = valid ? dot * sssa[s] : -CUDART_INF_F;
        if (ln == 0) g_scores[(size_t)b * NWORDS + s * WML + w] = score;

        if (valid) {
            float mn = fmaxf(m, score);
            float sc = __expf(m - mn);      /* m=-inf -> 0, no NaN */
            float p  = __expf(score - mn);
            l = l * sc + p;
            a0.x = a0.x*sc + p*v0.x; a0.y = a0.y*sc + p*v0.y;
            a0.z = a0.z*sc + p*v0.z; a0.w = a0.w*sc + p*v0.w;
            a1.x = a1.x*sc + p*v1.x; a1.y = a1.y*sc + p*v1.y;
            a1.z = a1.z*sc + p*v1.z; a1.w = a1.w*sc + p*v1.w;
            a2.x = a2.x*sc + p*v2.x; a2.y = a2.y*sc + p*v2.y;
            a2.z = a2.z*sc + p*v2.z; a2.w = a2.w*sc + p*v2.w;
            a3.x = a3.x*sc + p*v3.x; a3.y = a3.y*sc + p*v3.y;
            a3.z = a3.z*sc + p*v3.z; a3.w = a3.w*sc + p*v3.w;
            m = mn;
        }
    }

    float4* r4 = (float4*)racc[wp];
    r4[ln] = a0; r4[ln + 32] = a1; r4[ln + 64] = a2; r4[ln + 96] = a3;
    if (ln == 0) { rm[wp] = m; rl[wp] = l; }
    __syncthreads();

    float mC = -CUDART_INF_F;
    #pragma unroll
    for (int i = 0; i < 8; i++) mC = fmaxf(mC, rm[i]);

    #pragma unroll
    for (int rr = 0; rr < 2; rr++) {
        const int d = tid + rr * 256;
        float sacc = 0.f;
        #pragma unroll
        for (int i = 0; i < 8; i++) {
            float sc = (rm[i] == -CUDART_INF_F) ? 0.f : __expf(rm[i] - mC);
            sacc += racc[i][d] * sc;
        }
        g_partAcc[((size_t)b * WSPLIT + sp) * DIM + d] = sacc;
    }
    if (tid == 0) {
        float L = 0.f;
        #pragma unroll
        for (int i = 0; i < 8; i++) {
            float sc = (rm[i] == -CUDART_INF_F) ? 0.f : __expf(rm[i] - mC);
            L += rl[i] * sc;
        }
        g_partM[b * WSPLIT + sp] = mC;
        g_partL[b * WSPLIT + sp] = L;
    }
}

/* ------------------- K3a: merge splits, write c and align_vectors ----- */
__global__ void combine_kernel(float* __restrict__ align_out, int has_align) {
    const int b = blockIdx.x, tid = threadIdx.x;   /* 512 threads */
    __shared__ float sScale[WSPLIT];
    __shared__ float sM, sL;

    if (tid == 0) {
        float M = -CUDART_INF_F;
        #pragma unroll
        for (int i = 0; i < WSPLIT; i++) M = fmaxf(M, g_partM[b * WSPLIT + i]);
        float L = 0.f;
        #pragma unroll
        for (int i = 0; i < WSPLIT; i++) {
            float mi = g_partM[b * WSPLIT + i];
            float sc = (mi == -CUDART_INF_F) ? 0.f : __expf(mi - M);
            sScale[i] = sc;
            L += g_partL[b * WSPLIT + i] * sc;
        }
        sM = M; sL = L;
    }
    __syncthreads();
    const float M = sM;
    const float invL = 1.f / sL;

    float c = 0.f;
    #pragma unroll
    for (int i = 0; i < WSPLIT; i++)
        c += g_partAcc[((size_t)b * WSPLIT + i) * DIM + tid] * sScale[i];
    g_c[b * DIM + tid] = c * invL;

    if (has_align) {
        for (int n = tid; n < NWORDS; n += 512) {
            float s = g_scores[(size_t)b * NWORDS + n];
            align_out[(size_t)b * NWORDS + n] = __expf(s - M) * invL + 1e-20f;
        }
    }
}

/* ------------------- K3b: attn_h = tanh([c, source] @ W_out^T) -------- */
__global__ void outproj_kernel(const float* __restrict__ src,
                               const float* __restrict__ Wout,
                               float* __restrict__ attn_out) {
    const int dt = blockIdx.x * 64;
    __shared__ float As[64][65];
    __shared__ float Bs[64][65];
    const int tid = threadIdx.x;
    const int tx = tid & 15, ty = tid >> 4;
    float acc[4][4] = {};

    for (int k0 = 0; k0 < 2 * DIM; k0 += 64) {
        for (int i = tid; i < 4096; i += 256) {
            int r = i >> 6, c = i & 63;
            int k = k0 + c;
            As[r][c] = (k < DIM) ? g_c[r * DIM + k] : src[r * DIM + (k - DIM)];
            Bs[r][c] = Wout[(dt + r) * (2 * DIM) + k];
        }
        __syncthreads();
        #pragma unroll 8
        for (int kk = 0; kk < 64; kk++) {
            float a[4], w[4];
            #pragma unroll
            for (int i = 0; i < 4; i++) a[i] = As[ty * 4 + i][kk];
            #pragma unroll
            for (int j = 0; j < 4; j++) w[j] = Bs[tx * 4 + j][kk];
            #pragma unroll
            for (int i = 0; i < 4; i++)
                #pragma unroll
                for (int j = 0; j < 4; j++) acc[i][j] += a[i] * w[j];
        }
        __syncthreads();
    }
    #pragma unroll
    for (int i = 0; i < 4; i++)
        #pragma unroll
        for (int j = 0; j < 4; j++)
            attn_out[(ty * 4 + i) * DIM + dt + tx * 4 + j] = tanhf(acc[i][j]);
}

/* ------------------- launch ------------------------------------------- */
extern "C" void kernel_launch(void* const* d_in, const int* in_sizes, int n_in,
                              void* d_out, int out_size) {
    const float* source       = (const float*)d_in[0];
    const float* word_bank    = (const float*)d_in[1];
    const int*   word_lengths = (const int*)  d_in[2];
    const float* sent_bank    = (const float*)d_in[3];
    /* d_in[4] = sent_lengths: unused by the forward math */
    const float* static_attn  = (const float*)d_in[5];
    const float* W_word       = (const float*)d_in[6];
    const float* W_sent       = (const float*)d_in[7];
    const float* W_out        = (const float*)d_in[8];

    float* attn_out  = (float*)d_out;
    const int need   = BATCH * DIM + BATCH * NWORDS;
    const int has_align = (out_size >= need) ? 1 : 0;
    float* align_out = attn_out + BATCH * DIM;

    qproj_kernel<<<dim3(DIM / 64, 2), 256>>>(source, W_word, W_sent);
    sentscore_kernel<<<BATCH, 256>>>(sent_bank, static_attn);
    main_kernel<<<dim3(WSPLIT, BATCH), 256>>>(word_bank, word_lengths);
    combine_kernel<<<BATCH, DIM>>>(align_out, has_align);
    outproj_kernel<<<DIM / 64, 256>>>(source, W_out, attn_out);
}